// round 9
// baseline (speedup 1.0000x reference)
#include <cuda_runtime.h>
#include <math.h>

#define BATCH 1024
#define NIN   512
#define NHID  256

// ---------------------------------------------------------------------------
// Device-global scratch (no allocation allowed anywhere).
// ---------------------------------------------------------------------------
__device__ unsigned g_mT1[16 * NHID];        // transposed bitmask [w][node], layer1
__device__ unsigned g_mT2[8 * NIN];          // transposed bitmask [w][node], layer2

// ---------------------------------------------------------------------------
// Gumbel hard-select: forward value is exactly one-hot of argmax(logits + g).
// ---------------------------------------------------------------------------
__device__ __forceinline__ float gumbel_f(float u) {
    u = fminf(fmaxf(u, 1e-10f), 1.0f);
    return -logf(-logf(u));
}

// Per-warp mask dtype detection: 2 lane-parallel loads + ballots.
__device__ __forceinline__ int warp_detect(const void* p, int lane) {
    const unsigned* pw = (const unsigned*)p;
    unsigned a = pw[lane], b = pw[lane + 32];
    bool i32 = (a <= 1u) && (b <= 1u);
    bool f32 = (a == 0u || a == 0x3F800000u) && (b == 0u || b == 0x3F800000u);
    i32 = __all_sync(0xffffffffu, i32);
    f32 = __all_sync(0xffffffffu, f32);
    return i32 ? 2 : (f32 ? 3 : 1);
}

__device__ __forceinline__ bool mask_at(const void* p, int mode, int e) {
    if (mode == 2) return ((const int*)p)[e] != 0;
    if (mode == 3) return ((const float*)p)[e] != 0.0f;
    return ((const unsigned char*)p)[e] != 0;
}

// Transposed bit-packed masks. One warp packs 4 words (coalesced + MLP).
__global__ void __launch_bounds__(256) prep_masks_kernel(const void* __restrict__ m1,
                                                         const void* __restrict__ m2) {
    const int gw   = (blockIdx.x * 256 + threadIdx.x) >> 5;   // 0..2047
    const int lane = threadIdx.x & 31;
    if (gw < 1024) {
        const int mode = warp_detect(m1, lane);
        #pragma unroll
        for (int q = 0; q < 4; q++) {
            int wi = gw * 4 + q;
            int node = wi >> 4, w = wi & 15;
            bool b = mask_at(m1, mode, node * NIN + w * 32 + lane);
            unsigned bits = __ballot_sync(0xffffffffu, b);
            if (lane == 0) g_mT1[w * NHID + node] = bits;
        }
    } else {
        const int mode = warp_detect(m2, lane);
        #pragma unroll
        for (int q = 0; q < 4; q++) {
            int wi = (gw - 1024) * 4 + q;
            int node = wi >> 3, w = wi & 7;
            bool b = mask_at(m2, mode, node * NHID + w * 32 + lane);
            unsigned bits = __ballot_sync(0xffffffffu, b);
            if (lane == 0) g_mT2[w * NIN + node] = bits;
        }
    }
}

// ---------------------------------------------------------------------------
// Warp bitonic sort of 32*R u32 keys, ascending. Element i = lane*R + r.
// ---------------------------------------------------------------------------
template<int R, int J>
__device__ __forceinline__ void inreg_pass(unsigned* key, int lane, int k) {
    if (2 * J > k) return;
    #pragma unroll
    for (int r = 0; r < R; r++) {
        if ((r & J) == 0) {
            bool asc = (((unsigned)(lane * R + r) & (unsigned)k) == 0);
            unsigned a = key[r], b = key[r + J];
            unsigned mn = a < b ? a : b;
            unsigned mx = a < b ? b : a;
            key[r]     = asc ? mn : mx;
            key[r + J] = asc ? mx : mn;
        }
    }
}

template<int R>
__device__ __forceinline__ void bitonic_sort_warp(unsigned* key) {
    const int lane = threadIdx.x & 31;
    const int N = 32 * R;
    for (int k = 2; k <= N; k <<= 1) {
        for (int m = (k >> 1) / R; m >= 1; m >>= 1) {
            #pragma unroll
            for (int r = 0; r < R; r++) {
                unsigned a = key[r];
                unsigned b = __shfl_xor_sync(0xffffffffu, a, m);
                bool asc   = (((unsigned)(lane * R + r) & (unsigned)k) == 0);
                bool lower = ((lane & m) == 0);
                unsigned mn = a < b ? a : b;
                unsigned mx = a < b ? b : a;
                key[r] = (lower == asc) ? mn : mx;
            }
        }
        if (R >= 16) inreg_pass<R, 8>(key, lane, k);
        if (R >= 8)  inreg_pass<R, 4>(key, lane, k);
        inreg_pass<R, 2>(key, lane, k);
        inreg_pass<R, 1>(key, lane, k);
    }
}

// Ascending bitonic MERGE of 32*R elements held by one warp (element = lane*R+r).
template<int R, int J>
__device__ __forceinline__ void inreg_merge_asc(unsigned* key) {
    #pragma unroll
    for (int r = 0; r < R; r++) {
        if ((r & J) == 0) {
            unsigned a = key[r], b = key[r + J];
            key[r]     = a < b ? a : b;
            key[r + J] = a < b ? b : a;
        }
    }
}

template<int R>
__device__ __forceinline__ void bitonic_merge_asc(unsigned* key) {
    const int lane = threadIdx.x & 31;
    #pragma unroll
    for (int m = 16; m >= 1; m >>= 1) {
        #pragma unroll
        for (int r = 0; r < R; r++) {
            unsigned a = key[r];
            unsigned b = __shfl_xor_sync(0xffffffffu, a, m);
            bool lower = ((lane & m) == 0);
            unsigned mn = a < b ? a : b;
            unsigned mx = a < b ? b : a;
            key[r] = lower ? mn : mx;
        }
    }
    if (R >= 8) inreg_merge_asc<R, 4>(key);
    if (R >= 4) inreg_merge_asc<R, 2>(key);
    inreg_merge_asc<R, 1>(key);
}

template<int R>
__device__ __forceinline__ void invert_keys(unsigned* key) {
    #pragma unroll
    for (int r = 0; r < R; r++) key[r] = ~key[r];
}

// ---------------------------------------------------------------------------
// Mega-fused kernel: BOTH layers for ONE batch row per block, 1024 blocks.
// Warps 0-1: 2-warp cooperative sorts (halves asc/desc via bitwise-NOT, one
// smem exchange for the top merge step, then warp-local ascending merge).
// Warps 2-7: stage masks + values + sel. Walks are 2-step t-unrolled.
// ---------------------------------------------------------------------------
struct SmemLayout {
    unsigned      keys1[NIN];           // 2 KB (also sort exchange buffer)
    float         vals1[NIN];           // 2 KB
    unsigned      mask1[16 * NHID];     // 16 KB
    unsigned      mask2[8 * NIN];       // 16 KB
    float         h[NHID];              // 1 KB
    unsigned      keys2[NHID];          // 1 KB
    unsigned char sel1[NHID];
    unsigned char sel2[NIN];
};

__global__ void __launch_bounds__(256) mega_kernel(const float* __restrict__ x,
                                                   float* __restrict__ out,
                                                   const float* __restrict__ logits1,
                                                   const float* __restrict__ u1,
                                                   const float* __restrict__ logits2,
                                                   const float* __restrict__ u2) {
    __shared__ SmemLayout S;

    const int tid  = threadIdx.x;
    const int warp = tid >> 5;
    const int lane = tid & 31;
    const int row  = blockIdx.x;

    // ============ Phase 1: local half-sorts (warps 0-1) | staging (2-7) ======
    unsigned key[8];                      // persists across the exchange barriers
    const int half = warp;                // 0 = low half (asc), 1 = high (desc)

    if (warp < 2) {
        // load my 256-element half of the x row (coalesced 2×float4/lane)
        const float* src = x + (size_t)row * NIN + half * 256 + lane * 8;
        #pragma unroll
        for (int rr = 0; rr < 8; rr += 4) {
            float4 v = *(const float4*)(src + rr);
            float vv[4] = {v.x, v.y, v.z, v.w};
            #pragma unroll
            for (int q = 0; q < 4; q++) {
                int c = half * 256 + lane * 8 + rr + q;     // global element idx
                key[rr + q] = (__float_as_uint(vv[q]) & ~(unsigned)(NIN - 1)) | (unsigned)c;
            }
        }
        if (half) invert_keys<8>(key);
        bitonic_sort_warp<8>(key);        // asc on (possibly inverted) keys
        if (half) invert_keys<8>(key);    // now desc
        #pragma unroll
        for (int rr = 0; rr < 8; rr++)
            S.keys1[half * 256 + lane * 8 + rr] = key[rr];
    } else {
        const int t2 = tid - 64;   // 0..191
        const uint4* m14 = (const uint4*)g_mT1;
        const uint4* m24 = (const uint4*)g_mT2;
        uint4* sm14 = (uint4*)S.mask1;
        uint4* sm24 = (uint4*)S.mask2;
        for (int i = t2; i < (16 * NHID) / 4; i += 192) sm14[i] = m14[i];
        for (int i = t2; i < (8 * NIN) / 4; i += 192)  sm24[i] = m24[i];
        const float4* in4 = (const float4*)(x + (size_t)row * NIN);
        float4* sv4 = (float4*)S.vals1;
        for (int i = t2; i < NIN / 4; i += 192) sv4[i] = in4[i];
        for (int n = t2; n < NHID; n += 192) {
            float z0 = logits1[2 * n]     + gumbel_f(u1[2 * n]);
            float z1 = logits1[2 * n + 1] + gumbel_f(u1[2 * n + 1]);
            S.sel1[n] = (z1 > z0) ? 1 : 0;
        }
        for (int n = t2; n < NIN; n += 192) {
            float z0 = logits2[2 * n]     + gumbel_f(u2[2 * n]);
            float z1 = logits2[2 * n + 1] + gumbel_f(u2[2 * n + 1]);
            S.sel2[n] = (z1 > z0) ? 1 : 0;
        }
    }
    __syncthreads();

    // ============ Phase 1b: cross-warp merge step + warp-local merge =========
    if (warp < 2) {
        #pragma unroll
        for (int rr = 0; rr < 8; rr++) {
            unsigned p = S.keys1[(half ^ 1) * 256 + lane * 8 + rr];
            unsigned a = key[rr];
            key[rr] = half ? (a > p ? a : p) : (a < p ? a : p);
        }
        bitonic_merge_asc<8>(key);
    }
    __syncthreads();   // partner reads done before overwrite
    if (warp < 2) {
        #pragma unroll
        for (int rr = 0; rr < 8; rr++)
            S.keys1[half * 256 + lane * 8 + rr] = key[rr];
    }
    __syncthreads();

    // ============ Phase 2: layer-1 walk (node = tid), 2-step unroll ==========
    {
        const int node = tid;
        const int sel  = S.sel1[node];
        const unsigned posm = sel ? (unsigned)(NIN - 1) : 0u;
        float v = sel ? 0.0f : 1.0f;      // empty-mask identity
        bool  f = false;
        for (int t = 0; t < NIN && !f; t += 2) {
            unsigned k0 = S.keys1[(unsigned)t ^ posm];
            unsigned k1 = S.keys1[(unsigned)(t + 1) ^ posm];
            int i0 = (int)(k0 & (unsigned)(NIN - 1));
            int i1 = (int)(k1 & (unsigned)(NIN - 1));
            unsigned m0 = S.mask1[(i0 >> 5) * NHID + node];
            unsigned m1 = S.mask1[(i1 >> 5) * NHID + node];
            bool h0 = (m0 >> (i0 & 31)) & 1u;
            bool h1 = (m1 >> (i1 & 31)) & 1u;
            if (h0)      { v = S.vals1[i0]; f = true; }
            else if (h1) { v = S.vals1[i1]; f = true; }
        }
        S.h[node] = fmaxf(v, 0.0f);
    }
    __syncthreads();

    // ============ Phase 3: cooperative sort of the h row (warps 0-1) =========
    if (warp < 2) {
        #pragma unroll
        for (int rr = 0; rr < 4; rr++) {
            int c = half * 128 + lane * 4 + rr;
            float hv = S.h[c];
            key[rr] = (__float_as_uint(hv) & ~(unsigned)(NHID - 1)) | (unsigned)c;
        }
        if (half) invert_keys<4>(key);
        bitonic_sort_warp<4>(key);
        if (half) invert_keys<4>(key);
        #pragma unroll
        for (int rr = 0; rr < 4; rr++)
            S.keys2[half * 128 + lane * 4 + rr] = key[rr];
    }
    __syncthreads();
    if (warp < 2) {
        #pragma unroll
        for (int rr = 0; rr < 4; rr++) {
            unsigned p = S.keys2[(half ^ 1) * 128 + lane * 4 + rr];
            unsigned a = key[rr];
            key[rr] = half ? (a > p ? a : p) : (a < p ? a : p);
        }
        bitonic_merge_asc<4>(key);
    }
    __syncthreads();
    if (warp < 2) {
        #pragma unroll
        for (int rr = 0; rr < 4; rr++)
            S.keys2[half * 128 + lane * 4 + rr] = key[rr];
    }
    __syncthreads();

    // ============ Phase 4: layer-2 walk (2 nodes/thread, 2-step unroll) ======
    {
        unsigned posm[2]; float v[2]; bool f[2];
        #pragma unroll
        for (int np = 0; np < 2; np++) {
            const int node = np * 256 + tid;
            const int sel  = S.sel2[node];
            posm[np] = sel ? (unsigned)(NHID - 1) : 0u;
            v[np] = sel ? 0.0f : 1.0f;
            f[np] = false;
        }
        for (int t = 0; t < NHID; t += 2) {
            bool alldone = true;
            #pragma unroll
            for (int np = 0; np < 2; np++) {
                if (!f[np]) {
                    const int node = np * 256 + tid;
                    unsigned k0 = S.keys2[(unsigned)t ^ posm[np]];
                    unsigned k1 = S.keys2[(unsigned)(t + 1) ^ posm[np]];
                    int i0 = (int)(k0 & (unsigned)(NHID - 1));
                    int i1 = (int)(k1 & (unsigned)(NHID - 1));
                    unsigned m0 = S.mask2[(i0 >> 5) * NIN + node];
                    unsigned m1 = S.mask2[(i1 >> 5) * NIN + node];
                    bool h0 = (m0 >> (i0 & 31)) & 1u;
                    bool h1 = (m1 >> (i1 & 31)) & 1u;
                    if (h0)      { v[np] = S.h[i0]; f[np] = true; }
                    else if (h1) { v[np] = S.h[i1]; f[np] = true; }
                }
                alldone &= f[np];
            }
            if (alldone) break;
        }
        #pragma unroll
        for (int np = 0; np < 2; np++) {
            const int node = np * 256 + tid;
            out[(size_t)row * NIN + node] = fmaxf(v[np], 0.0f);
        }
    }
}

// ---------------------------------------------------------------------------
// kernel_launch: masks -> mega (both layers). Two launches.
// ---------------------------------------------------------------------------
extern "C" void kernel_launch(void* const* d_in, const int* in_sizes, int n_in,
                              void* d_out, int out_size) {
    const float* x       = (const float*)d_in[0];
    const float* logits1 = (const float*)d_in[1];
    const float* u1      = (const float*)d_in[2];
    const float* logits2 = (const float*)d_in[3];
    const float* u2      = (const float*)d_in[4];
    const void*  mask1   = d_in[5];
    const void*  mask2   = d_in[6];
    float* out = (float*)d_out;
    (void)in_sizes; (void)n_in; (void)out_size;

    prep_masks_kernel<<<256, 256>>>(mask1, mask2);
    mega_kernel<<<BATCH, 256>>>(x, out, logits1, u1, logits2, u2);
}

// round 10
// speedup vs baseline: 1.0437x; 1.0437x over previous
#include <cuda_runtime.h>
#include <math.h>

#define BATCH 1024
#define NIN   512
#define NHID  256

// ---------------------------------------------------------------------------
// Device-global scratch (no allocation allowed anywhere).
// ---------------------------------------------------------------------------
__device__ unsigned      g_mT1[16 * NHID];   // transposed bitmask [w][node], layer1
__device__ unsigned      g_mT2[8 * NIN];     // transposed bitmask [w][node], layer2
__device__ unsigned char g_sel1[NHID];       // 1 = max-node, 0 = min-node
__device__ unsigned char g_sel2[NIN];

// ---------------------------------------------------------------------------
// Gumbel hard-select: forward value is exactly one-hot of argmax(logits + g).
// ---------------------------------------------------------------------------
__device__ __forceinline__ float gumbel_f(float u) {
    u = fminf(fmaxf(u, 1e-10f), 1.0f);
    return -logf(-logf(u));
}

// Per-warp mask dtype detection: 2 lane-parallel loads + ballots.
__device__ __forceinline__ int warp_detect(const void* p, int lane) {
    const unsigned* pw = (const unsigned*)p;
    unsigned a = pw[lane], b = pw[lane + 32];
    bool i32 = (a <= 1u) && (b <= 1u);
    bool f32 = (a == 0u || a == 0x3F800000u) && (b == 0u || b == 0x3F800000u);
    i32 = __all_sync(0xffffffffu, i32);
    f32 = __all_sync(0xffffffffu, f32);
    return i32 ? 2 : (f32 ? 3 : 1);
}

__device__ __forceinline__ bool mask_at(const void* p, int mode, int e) {
    if (mode == 2) return ((const int*)p)[e] != 0;
    if (mode == 3) return ((const float*)p)[e] != 0.0f;
    return ((const unsigned char*)p)[e] != 0;
}

// Prep: blocks 0..255 pack masks (one warp -> 4 words, coalesced + MLP);
// block 256 computes node sel for both layers (once per launch, not per block).
__global__ void __launch_bounds__(256) prep_kernel(const void* __restrict__ m1,
                                                   const void* __restrict__ m2,
                                                   const float* __restrict__ logits1,
                                                   const float* __restrict__ u1,
                                                   const float* __restrict__ logits2,
                                                   const float* __restrict__ u2) {
    if (blockIdx.x == 256) {
        int n = threadIdx.x;
        {
            float z0 = logits1[2 * n]     + gumbel_f(u1[2 * n]);
            float z1 = logits1[2 * n + 1] + gumbel_f(u1[2 * n + 1]);
            g_sel1[n] = (z1 > z0) ? 1 : 0;
        }
        #pragma unroll
        for (int q = 0; q < 2; q++) {
            int j = q * 256 + n;
            float z0 = logits2[2 * j]     + gumbel_f(u2[2 * j]);
            float z1 = logits2[2 * j + 1] + gumbel_f(u2[2 * j + 1]);
            g_sel2[j] = (z1 > z0) ? 1 : 0;
        }
        return;
    }
    const int gw   = (blockIdx.x * 256 + threadIdx.x) >> 5;   // 0..2047
    const int lane = threadIdx.x & 31;
    if (gw < 1024) {
        const int mode = warp_detect(m1, lane);
        #pragma unroll
        for (int q = 0; q < 4; q++) {
            int wi = gw * 4 + q;
            int node = wi >> 4, w = wi & 15;
            bool b = mask_at(m1, mode, node * NIN + w * 32 + lane);
            unsigned bits = __ballot_sync(0xffffffffu, b);
            if (lane == 0) g_mT1[w * NHID + node] = bits;
        }
    } else {
        const int mode = warp_detect(m2, lane);
        #pragma unroll
        for (int q = 0; q < 4; q++) {
            int wi = (gw - 1024) * 4 + q;
            int node = wi >> 3, w = wi & 7;
            bool b = mask_at(m2, mode, node * NHID + w * 32 + lane);
            unsigned bits = __ballot_sync(0xffffffffu, b);
            if (lane == 0) g_mT2[w * NIN + node] = bits;
        }
    }
}

// ---------------------------------------------------------------------------
// Warp bitonic sort of 32*R u32 keys, ascending. Element i = lane*R + r.
// ---------------------------------------------------------------------------
template<int R, int J>
__device__ __forceinline__ void inreg_pass(unsigned* key, int lane, int k) {
    if (2 * J > k) return;
    #pragma unroll
    for (int r = 0; r < R; r++) {
        if ((r & J) == 0) {
            bool asc = (((unsigned)(lane * R + r) & (unsigned)k) == 0);
            unsigned a = key[r], b = key[r + J];
            unsigned mn = a < b ? a : b;
            unsigned mx = a < b ? b : a;
            key[r]     = asc ? mn : mx;
            key[r + J] = asc ? mx : mn;
        }
    }
}

template<int R>
__device__ __forceinline__ void bitonic_sort_warp(unsigned* key) {
    const int lane = threadIdx.x & 31;
    const int N = 32 * R;
    for (int k = 2; k <= N; k <<= 1) {
        for (int m = (k >> 1) / R; m >= 1; m >>= 1) {
            #pragma unroll
            for (int r = 0; r < R; r++) {
                unsigned a = key[r];
                unsigned b = __shfl_xor_sync(0xffffffffu, a, m);
                bool asc   = (((unsigned)(lane * R + r) & (unsigned)k) == 0);
                bool lower = ((lane & m) == 0);
                unsigned mn = a < b ? a : b;
                unsigned mx = a < b ? b : a;
                key[r] = (lower == asc) ? mn : mx;
            }
        }
        if (R >= 16) inreg_pass<R, 8>(key, lane, k);
        if (R >= 8)  inreg_pass<R, 4>(key, lane, k);
        inreg_pass<R, 2>(key, lane, k);
        inreg_pass<R, 1>(key, lane, k);
    }
}

// Ascending bitonic MERGE of 32*R elements held by one warp.
template<int R, int J>
__device__ __forceinline__ void inreg_merge_asc(unsigned* key) {
    #pragma unroll
    for (int r = 0; r < R; r++) {
        if ((r & J) == 0) {
            unsigned a = key[r], b = key[r + J];
            key[r]     = a < b ? a : b;
            key[r + J] = a < b ? b : a;
        }
    }
}

template<int R>
__device__ __forceinline__ void bitonic_merge_asc(unsigned* key) {
    const int lane = threadIdx.x & 31;
    #pragma unroll
    for (int m = 16; m >= 1; m >>= 1) {
        #pragma unroll
        for (int r = 0; r < R; r++) {
            unsigned a = key[r];
            unsigned b = __shfl_xor_sync(0xffffffffu, a, m);
            bool lower = ((lane & m) == 0);
            unsigned mn = a < b ? a : b;
            unsigned mx = a < b ? b : a;
            key[r] = lower ? mn : mx;
        }
    }
    if (R >= 8) inreg_merge_asc<R, 4>(key);
    if (R >= 4) inreg_merge_asc<R, 2>(key);
    inreg_merge_asc<R, 1>(key);
}

template<int R>
__device__ __forceinline__ void invert_keys(unsigned* key) {
    #pragma unroll
    for (int r = 0; r < R; r++) key[r] = ~key[r];
}

// ---------------------------------------------------------------------------
// Mega-fused kernel: BOTH layers for ONE batch row per block, 1024 blocks.
// NO mask staging: walks read the bit-packed masks straight from L2 —
// idx is row-uniform and node = tid, so every probe is a coalesced block load.
// Smem footprint ~7 KB -> ~6 blocks/SM.
// ---------------------------------------------------------------------------
struct SmemLayout {
    unsigned      keys1[NIN];           // 2 KB (also sort exchange buffer)
    float         vals1[NIN];           // 2 KB
    float         h[NHID];              // 1 KB
    unsigned      keys2[NHID];          // 1 KB
    unsigned char sel1[NHID];           // 256 B
    unsigned char sel2[NIN];            // 512 B
};

__global__ void __launch_bounds__(256) mega_kernel(const float* __restrict__ x,
                                                   float* __restrict__ out) {
    __shared__ SmemLayout S;

    const int tid  = threadIdx.x;
    const int warp = tid >> 5;
    const int lane = tid & 31;
    const int row  = blockIdx.x;

    // ============ Phase 1: half-sorts (warps 0-1) | tiny staging (2-7) =======
    unsigned key[8];                      // persists across the exchange barriers
    const int half = warp;                // 0 = low half (asc), 1 = high (desc)

    if (warp < 2) {
        const float* src = x + (size_t)row * NIN + half * 256 + lane * 8;
        #pragma unroll
        for (int rr = 0; rr < 8; rr += 4) {
            float4 v = *(const float4*)(src + rr);
            float vv[4] = {v.x, v.y, v.z, v.w};
            #pragma unroll
            for (int q = 0; q < 4; q++) {
                int c = half * 256 + lane * 8 + rr + q;
                key[rr + q] = (__float_as_uint(vv[q]) & ~(unsigned)(NIN - 1)) | (unsigned)c;
            }
        }
        if (half) invert_keys<8>(key);
        bitonic_sort_warp<8>(key);
        if (half) invert_keys<8>(key);
        #pragma unroll
        for (int rr = 0; rr < 8; rr++)
            S.keys1[half * 256 + lane * 8 + rr] = key[rr];
    } else {
        const int t2 = tid - 64;   // 0..191
        // exact row values (128 float4)
        const float4* in4 = (const float4*)(x + (size_t)row * NIN);
        if (t2 < 128) ((float4*)S.vals1)[t2] = in4[t2];
        // sel bytes (precomputed): 64 + 128 uints
        const unsigned* s1 = (const unsigned*)g_sel1;
        const unsigned* s2 = (const unsigned*)g_sel2;
        if (t2 < 64)                 ((unsigned*)S.sel1)[t2]       = s1[t2];
        if (t2 >= 64 && t2 < 192)    ((unsigned*)S.sel2)[t2 - 64]  = s2[t2 - 64];
    }
    __syncthreads();

    // ============ Phase 1b: cross-warp merge step + warp-local merge =========
    if (warp < 2) {
        #pragma unroll
        for (int rr = 0; rr < 8; rr++) {
            unsigned p = S.keys1[(half ^ 1) * 256 + lane * 8 + rr];
            unsigned a = key[rr];
            key[rr] = half ? (a > p ? a : p) : (a < p ? a : p);
        }
        bitonic_merge_asc<8>(key);
    }
    __syncthreads();   // partner reads done before overwrite
    if (warp < 2) {
        #pragma unroll
        for (int rr = 0; rr < 8; rr++)
            S.keys1[half * 256 + lane * 8 + rr] = key[rr];
    }
    __syncthreads();

    // ============ Phase 2: layer-1 walk (node = tid), 4 probes in flight =====
    {
        const int node = tid;
        const int sel  = S.sel1[node];
        const unsigned posm = sel ? (unsigned)(NIN - 1) : 0u;
        float v = sel ? 0.0f : 1.0f;      // empty-mask identity
        bool  f = false;
        for (int t = 0; t < NIN && !f; t += 4) {
            int  idx[4]; bool hit[4];
            #pragma unroll
            for (int q = 0; q < 4; q++) {
                unsigned kk = S.keys1[(unsigned)(t + q) ^ posm];
                idx[q] = (int)(kk & (unsigned)(NIN - 1));
                hit[q] = (g_mT1[(idx[q] >> 5) * NHID + node] >> (idx[q] & 31)) & 1u;
            }
            #pragma unroll
            for (int q = 0; q < 4; q++)
                if (!f && hit[q]) { v = S.vals1[idx[q]]; f = true; }
        }
        S.h[node] = fmaxf(v, 0.0f);
    }
    __syncthreads();

    // ============ Phase 3: cooperative sort of the h row (warps 0-1) =========
    if (warp < 2) {
        #pragma unroll
        for (int rr = 0; rr < 4; rr++) {
            int c = half * 128 + lane * 4 + rr;
            float hv = S.h[c];
            key[rr] = (__float_as_uint(hv) & ~(unsigned)(NHID - 1)) | (unsigned)c;
        }
        if (half) invert_keys<4>(key);
        bitonic_sort_warp<4>(key);
        if (half) invert_keys<4>(key);
        #pragma unroll
        for (int rr = 0; rr < 4; rr++)
            S.keys2[half * 128 + lane * 4 + rr] = key[rr];
    }
    __syncthreads();
    if (warp < 2) {
        #pragma unroll
        for (int rr = 0; rr < 4; rr++) {
            unsigned p = S.keys2[(half ^ 1) * 128 + lane * 4 + rr];
            unsigned a = key[rr];
            key[rr] = half ? (a > p ? a : p) : (a < p ? a : p);
        }
        bitonic_merge_asc<4>(key);
    }
    __syncthreads();
    if (warp < 2) {
        #pragma unroll
        for (int rr = 0; rr < 4; rr++)
            S.keys2[half * 128 + lane * 4 + rr] = key[rr];
    }
    __syncthreads();

    // ============ Phase 4: layer-2 walk (2 nodes/thread, 4 probes in flight) =
    {
        unsigned posm[2]; float v[2]; bool f[2];
        #pragma unroll
        for (int np = 0; np < 2; np++) {
            const int node = np * 256 + tid;
            const int sel  = S.sel2[node];
            posm[np] = sel ? (unsigned)(NHID - 1) : 0u;
            v[np] = sel ? 0.0f : 1.0f;
            f[np] = false;
        }
        for (int t = 0; t < NHID; t += 2) {
            bool alldone = true;
            #pragma unroll
            for (int np = 0; np < 2; np++) {
                if (!f[np]) {
                    const int node = np * 256 + tid;
                    unsigned k0 = S.keys2[(unsigned)t ^ posm[np]];
                    unsigned k1 = S.keys2[(unsigned)(t + 1) ^ posm[np]];
                    int i0 = (int)(k0 & (unsigned)(NHID - 1));
                    int i1 = (int)(k1 & (unsigned)(NHID - 1));
                    unsigned m0 = g_mT2[(i0 >> 5) * NIN + node];
                    unsigned m1 = g_mT2[(i1 >> 5) * NIN + node];
                    bool h0 = (m0 >> (i0 & 31)) & 1u;
                    bool h1 = (m1 >> (i1 & 31)) & 1u;
                    if (h0)      { v[np] = S.h[i0]; f[np] = true; }
                    else if (h1) { v[np] = S.h[i1]; f[np] = true; }
                }
                alldone &= f[np];
            }
            if (alldone) break;
        }
        #pragma unroll
        for (int np = 0; np < 2; np++) {
            const int node = np * 256 + tid;
            out[(size_t)row * NIN + node] = fmaxf(v[np], 0.0f);
        }
    }
}

// ---------------------------------------------------------------------------
// kernel_launch: prep (masks + sel) -> mega (both layers). Two launches.
// ---------------------------------------------------------------------------
extern "C" void kernel_launch(void* const* d_in, const int* in_sizes, int n_in,
                              void* d_out, int out_size) {
    const float* x       = (const float*)d_in[0];
    const float* logits1 = (const float*)d_in[1];
    const float* u1      = (const float*)d_in[2];
    const float* logits2 = (const float*)d_in[3];
    const float* u2      = (const float*)d_in[4];
    const void*  mask1   = d_in[5];
    const void*  mask2   = d_in[6];
    float* out = (float*)d_out;
    (void)in_sizes; (void)n_in; (void)out_size;

    prep_kernel<<<257, 256>>>(mask1, mask2, logits1, u1, logits2, u2);
    mega_kernel<<<BATCH, 256>>>(x, out);
}

// round 11
// speedup vs baseline: 1.0780x; 1.0329x over previous
#include <cuda_runtime.h>
#include <math.h>

#define BATCH 1024
#define NIN   512
#define NHID  256

// ---------------------------------------------------------------------------
// Device-global scratch (no allocation allowed anywhere).
// ---------------------------------------------------------------------------
__device__ unsigned      g_mT1[16 * NHID];   // transposed bitmask [w][node], layer1
__device__ unsigned      g_mT2[8 * NIN];     // transposed bitmask [w][node], layer2
__device__ unsigned char g_sel1[NHID];       // 1 = max-node, 0 = min-node
__device__ unsigned char g_sel2[NIN];

// ---------------------------------------------------------------------------
// Gumbel hard-select: forward value is exactly one-hot of argmax(logits + g).
// ---------------------------------------------------------------------------
__device__ __forceinline__ float gumbel_f(float u) {
    u = fminf(fmaxf(u, 1e-10f), 1.0f);
    return -logf(-logf(u));
}

// Per-warp mask dtype detection: 2 lane-parallel loads + ballots.
__device__ __forceinline__ int warp_detect(const void* p, int lane) {
    const unsigned* pw = (const unsigned*)p;
    unsigned a = pw[lane], b = pw[lane + 32];
    bool i32 = (a <= 1u) && (b <= 1u);
    bool f32 = (a == 0u || a == 0x3F800000u) && (b == 0u || b == 0x3F800000u);
    i32 = __all_sync(0xffffffffu, i32);
    f32 = __all_sync(0xffffffffu, f32);
    return i32 ? 2 : (f32 ? 3 : 1);
}

__device__ __forceinline__ bool mask_at(const void* p, int mode, int e) {
    if (mode == 2) return ((const int*)p)[e] != 0;
    if (mode == 3) return ((const float*)p)[e] != 0.0f;
    return ((const unsigned char*)p)[e] != 0;
}

// Prep: blocks 0..255 pack masks (one warp -> 4 words, coalesced + MLP);
// block 256 computes node sel for both layers.
__global__ void __launch_bounds__(256) prep_kernel(const void* __restrict__ m1,
                                                   const void* __restrict__ m2,
                                                   const float* __restrict__ logits1,
                                                   const float* __restrict__ u1,
                                                   const float* __restrict__ logits2,
                                                   const float* __restrict__ u2) {
    if (blockIdx.x == 256) {
        int n = threadIdx.x;
        {
            float z0 = logits1[2 * n]     + gumbel_f(u1[2 * n]);
            float z1 = logits1[2 * n + 1] + gumbel_f(u1[2 * n + 1]);
            g_sel1[n] = (z1 > z0) ? 1 : 0;
        }
        #pragma unroll
        for (int q = 0; q < 2; q++) {
            int j = q * 256 + n;
            float z0 = logits2[2 * j]     + gumbel_f(u2[2 * j]);
            float z1 = logits2[2 * j + 1] + gumbel_f(u2[2 * j + 1]);
            g_sel2[j] = (z1 > z0) ? 1 : 0;
        }
        return;
    }
    const int gw   = (blockIdx.x * 256 + threadIdx.x) >> 5;   // 0..2047
    const int lane = threadIdx.x & 31;
    if (gw < 1024) {
        const int mode = warp_detect(m1, lane);
        #pragma unroll
        for (int q = 0; q < 4; q++) {
            int wi = gw * 4 + q;
            int node = wi >> 4, w = wi & 15;
            bool b = mask_at(m1, mode, node * NIN + w * 32 + lane);
            unsigned bits = __ballot_sync(0xffffffffu, b);
            if (lane == 0) g_mT1[w * NHID + node] = bits;
        }
    } else {
        const int mode = warp_detect(m2, lane);
        #pragma unroll
        for (int q = 0; q < 4; q++) {
            int wi = (gw - 1024) * 4 + q;
            int node = wi >> 3, w = wi & 7;
            bool b = mask_at(m2, mode, node * NHID + w * 32 + lane);
            unsigned bits = __ballot_sync(0xffffffffu, b);
            if (lane == 0) g_mT2[w * NIN + node] = bits;
        }
    }
}

// ---------------------------------------------------------------------------
// Warp bitonic sort of 32*R u32 keys, ascending. Element i = lane*R + r.
// ---------------------------------------------------------------------------
template<int R, int J>
__device__ __forceinline__ void inreg_pass(unsigned* key, int lane, int k) {
    if (2 * J > k) return;
    #pragma unroll
    for (int r = 0; r < R; r++) {
        if ((r & J) == 0) {
            bool asc = (((unsigned)(lane * R + r) & (unsigned)k) == 0);
            unsigned a = key[r], b = key[r + J];
            unsigned mn = a < b ? a : b;
            unsigned mx = a < b ? b : a;
            key[r]     = asc ? mn : mx;
            key[r + J] = asc ? mx : mn;
        }
    }
}

template<int R>
__device__ __forceinline__ void bitonic_sort_warp(unsigned* key) {
    const int lane = threadIdx.x & 31;
    const int N = 32 * R;
    for (int k = 2; k <= N; k <<= 1) {
        for (int m = (k >> 1) / R; m >= 1; m >>= 1) {
            #pragma unroll
            for (int r = 0; r < R; r++) {
                unsigned a = key[r];
                unsigned b = __shfl_xor_sync(0xffffffffu, a, m);
                bool asc   = (((unsigned)(lane * R + r) & (unsigned)k) == 0);
                bool lower = ((lane & m) == 0);
                unsigned mn = a < b ? a : b;
                unsigned mx = a < b ? b : a;
                key[r] = (lower == asc) ? mn : mx;
            }
        }
        if (R >= 16) inreg_pass<R, 8>(key, lane, k);
        if (R >= 8)  inreg_pass<R, 4>(key, lane, k);
        inreg_pass<R, 2>(key, lane, k);
        inreg_pass<R, 1>(key, lane, k);
    }
}

// Ascending bitonic MERGE of 32*R elements held by one warp.
template<int R, int J>
__device__ __forceinline__ void inreg_merge_asc(unsigned* key) {
    #pragma unroll
    for (int r = 0; r < R; r++) {
        if ((r & J) == 0) {
            unsigned a = key[r], b = key[r + J];
            key[r]     = a < b ? a : b;
            key[r + J] = a < b ? b : a;
        }
    }
}

template<int R>
__device__ __forceinline__ void bitonic_merge_asc(unsigned* key) {
    const int lane = threadIdx.x & 31;
    #pragma unroll
    for (int m = 16; m >= 1; m >>= 1) {
        #pragma unroll
        for (int r = 0; r < R; r++) {
            unsigned a = key[r];
            unsigned b = __shfl_xor_sync(0xffffffffu, a, m);
            bool lower = ((lane & m) == 0);
            unsigned mn = a < b ? a : b;
            unsigned mx = a < b ? b : a;
            key[r] = lower ? mn : mx;
        }
    }
    if (R >= 8) inreg_merge_asc<R, 4>(key);
    if (R >= 4) inreg_merge_asc<R, 2>(key);
    inreg_merge_asc<R, 1>(key);
}

template<int R>
__device__ __forceinline__ void invert_keys(unsigned* key) {
    #pragma unroll
    for (int r = 0; r < R; r++) key[r] = ~key[r];
}

// ---------------------------------------------------------------------------
// Mega-fused kernel: 64-thread blocks, ONE row per block, 1024 blocks.
// BOTH warps always work: both cooperate on every sort (no spectator warps),
// walks are 4 chains/thread (layer 1) and 8 chains/thread (layer 2) with
// masks probed directly from L2 (coalesced: consecutive lanes = consecutive
// nodes). Smem ~7 KB.
// ---------------------------------------------------------------------------
struct SmemLayout {
    unsigned      keys1[NIN];           // 2 KB (also sort exchange buffer)
    float         vals1[NIN];           // 2 KB
    float         h[NHID];              // 1 KB
    unsigned      keys2[NHID];          // 1 KB
    unsigned char sel1[NHID];           // 256 B
    unsigned char sel2[NIN];            // 512 B
};

__global__ void __launch_bounds__(64) mega_kernel(const float* __restrict__ x,
                                                  float* __restrict__ out) {
    __shared__ SmemLayout S;

    const int tid  = threadIdx.x;       // 0..63
    const int half = tid >> 5;          // warp 0 = low half (asc), 1 = high (desc)
    const int lane = tid & 31;
    const int row  = blockIdx.x;

    // ============ Phase 1: both warps load + half-sort the x row =============
    unsigned key[8];
    {
        const float* src = x + (size_t)row * NIN + half * 256 + lane * 8;
        #pragma unroll
        for (int rr = 0; rr < 8; rr += 4) {
            float4 v = *(const float4*)(src + rr);
            // stash exact values while they're in registers
            *(float4*)(&S.vals1[half * 256 + lane * 8 + rr]) = v;
            float vv[4] = {v.x, v.y, v.z, v.w};
            #pragma unroll
            for (int q = 0; q < 4; q++) {
                int c = half * 256 + lane * 8 + rr + q;
                key[rr + q] = (__float_as_uint(vv[q]) & ~(unsigned)(NIN - 1)) | (unsigned)c;
            }
        }
        // sel staging: 64 + 128 uints over 64 threads
        ((unsigned*)S.sel1)[tid] = ((const unsigned*)g_sel1)[tid];
        ((unsigned*)S.sel2)[tid]      = ((const unsigned*)g_sel2)[tid];
        ((unsigned*)S.sel2)[tid + 64] = ((const unsigned*)g_sel2)[tid + 64];

        if (half) invert_keys<8>(key);
        bitonic_sort_warp<8>(key);
        if (half) invert_keys<8>(key);   // high half now descending
        #pragma unroll
        for (int rr = 0; rr < 8; rr++)
            S.keys1[half * 256 + lane * 8 + rr] = key[rr];
    }
    __syncthreads();

    // ============ Phase 1b: cross-warp merge step + warp-local merge =========
    {
        #pragma unroll
        for (int rr = 0; rr < 8; rr++) {
            unsigned p = S.keys1[(half ^ 1) * 256 + lane * 8 + rr];
            unsigned a = key[rr];
            key[rr] = half ? (a > p ? a : p) : (a < p ? a : p);
        }
        bitonic_merge_asc<8>(key);
    }
    __syncthreads();   // partner reads done before overwrite
    {
        #pragma unroll
        for (int rr = 0; rr < 8; rr++)
            S.keys1[half * 256 + lane * 8 + rr] = key[rr];
    }
    __syncthreads();

    // ============ Phase 2: layer-1 walk — 4 node-chains per thread ===========
    {
        bool  sel[4]; float v[4]; bool f[4];
        #pragma unroll
        for (int c = 0; c < 4; c++) {
            int node = c * 64 + tid;
            sel[c] = S.sel1[node] != 0;
            v[c] = sel[c] ? 0.0f : 1.0f;    // empty-mask identity
            f[c] = false;
        }
        for (int t = 0; t < NIN; t++) {
            unsigned kA = S.keys1[t];                   // ascending (min) probe
            unsigned kB = S.keys1[(NIN - 1) - t];       // descending (max) probe
            int iA = (int)(kA & (unsigned)(NIN - 1));
            int iB = (int)(kB & (unsigned)(NIN - 1));
            bool alldone = true;
            #pragma unroll
            for (int c = 0; c < 4; c++) {
                if (!f[c]) {
                    int node = c * 64 + tid;
                    int idx  = sel[c] ? iB : iA;
                    unsigned m = g_mT1[(idx >> 5) * NHID + node];   // coalesced L2
                    if ((m >> (idx & 31)) & 1u) { v[c] = S.vals1[idx]; f[c] = true; }
                }
                alldone &= f[c];
            }
            if (alldone) break;
        }
        #pragma unroll
        for (int c = 0; c < 4; c++)
            S.h[c * 64 + tid] = fmaxf(v[c], 0.0f);
    }
    __syncthreads();

    // ============ Phase 3: both warps cooperatively sort the h row ===========
    {
        #pragma unroll
        for (int rr = 0; rr < 4; rr++) {
            int c = half * 128 + lane * 4 + rr;
            float hv = S.h[c];
            key[rr] = (__float_as_uint(hv) & ~(unsigned)(NHID - 1)) | (unsigned)c;
        }
        if (half) invert_keys<4>(key);
        bitonic_sort_warp<4>(key);
        if (half) invert_keys<4>(key);
        #pragma unroll
        for (int rr = 0; rr < 4; rr++)
            S.keys2[half * 128 + lane * 4 + rr] = key[rr];
    }
    __syncthreads();
    {
        #pragma unroll
        for (int rr = 0; rr < 4; rr++) {
            unsigned p = S.keys2[(half ^ 1) * 128 + lane * 4 + rr];
            unsigned a = key[rr];
            key[rr] = half ? (a > p ? a : p) : (a < p ? a : p);
        }
        bitonic_merge_asc<4>(key);
    }
    __syncthreads();
    {
        #pragma unroll
        for (int rr = 0; rr < 4; rr++)
            S.keys2[half * 128 + lane * 4 + rr] = key[rr];
    }
    __syncthreads();

    // ============ Phase 4: layer-2 walk — 8 node-chains per thread ===========
    {
        bool  sel[8]; float v[8]; bool f[8];
        #pragma unroll
        for (int c = 0; c < 8; c++) {
            int node = c * 64 + tid;
            sel[c] = S.sel2[node] != 0;
            v[c] = sel[c] ? 0.0f : 1.0f;
            f[c] = false;
        }
        for (int t = 0; t < NHID; t++) {
            unsigned kA = S.keys2[t];
            unsigned kB = S.keys2[(NHID - 1) - t];
            int iA = (int)(kA & (unsigned)(NHID - 1));
            int iB = (int)(kB & (unsigned)(NHID - 1));
            bool alldone = true;
            #pragma unroll
            for (int c = 0; c < 8; c++) {
                if (!f[c]) {
                    int node = c * 64 + tid;
                    int idx  = sel[c] ? iB : iA;
                    unsigned m = g_mT2[(idx >> 5) * NIN + node];    // coalesced L2
                    if ((m >> (idx & 31)) & 1u) { v[c] = S.h[idx]; f[c] = true; }
                }
                alldone &= f[c];
            }
            if (alldone) break;
        }
        #pragma unroll
        for (int c = 0; c < 8; c++)
            out[(size_t)row * NIN + c * 64 + tid] = fmaxf(v[c], 0.0f);
    }
}

// ---------------------------------------------------------------------------
// kernel_launch: prep (masks + sel) -> mega (both layers). Two launches.
// ---------------------------------------------------------------------------
extern "C" void kernel_launch(void* const* d_in, const int* in_sizes, int n_in,
                              void* d_out, int out_size) {
    const float* x       = (const float*)d_in[0];
    const float* logits1 = (const float*)d_in[1];
    const float* u1      = (const float*)d_in[2];
    const float* logits2 = (const float*)d_in[3];
    const float* u2      = (const float*)d_in[4];
    const void*  mask1   = d_in[5];
    const void*  mask2   = d_in[6];
    float* out = (float*)d_out;
    (void)in_sizes; (void)n_in; (void)out_size;

    prep_kernel<<<257, 256>>>(mask1, mask2, logits1, u1, logits2, u2);
    mega_kernel<<<BATCH, 64>>>(x, out);
}

// round 13
// speedup vs baseline: 1.3476x; 1.2500x over previous
#include <cuda_runtime.h>
#include <math.h>

#define BATCH 1024
#define NIN   512
#define NHID  256

// ---------------------------------------------------------------------------
// Device-global scratch (no allocation allowed anywhere).
// ---------------------------------------------------------------------------
__device__ unsigned      g_mT1[16 * NHID];   // transposed bitmask [w][node], layer1
__device__ unsigned      g_mT2[8 * NIN];     // transposed bitmask [w][node], layer2
__device__ unsigned char g_sel1[NHID];       // 1 = max-node, 0 = min-node
__device__ unsigned char g_sel2[NIN];

// ---------------------------------------------------------------------------
// Gumbel hard-select: forward value is exactly one-hot of argmax(logits + g).
// ---------------------------------------------------------------------------
__device__ __forceinline__ float gumbel_f(float u) {
    u = fminf(fmaxf(u, 1e-10f), 1.0f);
    return -logf(-logf(u));
}

// Per-warp mask dtype detection: 2 lane-parallel loads + ballots.
__device__ __forceinline__ int warp_detect(const void* p, int lane) {
    const unsigned* pw = (const unsigned*)p;
    unsigned a = pw[lane], b = pw[lane + 32];
    bool i32 = (a <= 1u) && (b <= 1u);
    bool f32 = (a == 0u || a == 0x3F800000u) && (b == 0u || b == 0x3F800000u);
    i32 = __all_sync(0xffffffffu, i32);
    f32 = __all_sync(0xffffffffu, f32);
    return i32 ? 2 : (f32 ? 3 : 1);
}

__device__ __forceinline__ bool mask_at(const void* p, int mode, int e) {
    if (mode == 2) return ((const int*)p)[e] != 0;
    if (mode == 3) return ((const float*)p)[e] != 0.0f;
    return ((const unsigned char*)p)[e] != 0;
}

// Prep: blocks 0..255 pack masks (one warp -> 4 words, coalesced + MLP);
// block 256 computes node sel for both layers.
__global__ void __launch_bounds__(256) prep_kernel(const void* __restrict__ m1,
                                                   const void* __restrict__ m2,
                                                   const float* __restrict__ logits1,
                                                   const float* __restrict__ u1,
                                                   const float* __restrict__ logits2,
                                                   const float* __restrict__ u2) {
    if (blockIdx.x == 256) {
        int n = threadIdx.x;
        {
            float z0 = logits1[2 * n]     + gumbel_f(u1[2 * n]);
            float z1 = logits1[2 * n + 1] + gumbel_f(u1[2 * n + 1]);
            g_sel1[n] = (z1 > z0) ? 1 : 0;
        }
        #pragma unroll
        for (int q = 0; q < 2; q++) {
            int j = q * 256 + n;
            float z0 = logits2[2 * j]     + gumbel_f(u2[2 * j]);
            float z1 = logits2[2 * j + 1] + gumbel_f(u2[2 * j + 1]);
            g_sel2[j] = (z1 > z0) ? 1 : 0;
        }
        return;
    }
    const int gw   = (blockIdx.x * 256 + threadIdx.x) >> 5;   // 0..2047
    const int lane = threadIdx.x & 31;
    if (gw < 1024) {
        const int mode = warp_detect(m1, lane);
        #pragma unroll
        for (int q = 0; q < 4; q++) {
            int wi = gw * 4 + q;
            int node = wi >> 4, w = wi & 15;
            bool b = mask_at(m1, mode, node * NIN + w * 32 + lane);
            unsigned bits = __ballot_sync(0xffffffffu, b);
            if (lane == 0) g_mT1[w * NHID + node] = bits;
        }
    } else {
        const int mode = warp_detect(m2, lane);
        #pragma unroll
        for (int q = 0; q < 4; q++) {
            int wi = (gw - 1024) * 4 + q;
            int node = wi >> 3, w = wi & 7;
            bool b = mask_at(m2, mode, node * NHID + w * 32 + lane);
            unsigned bits = __ballot_sync(0xffffffffu, b);
            if (lane == 0) g_mT2[w * NIN + node] = bits;
        }
    }
}

// ---------------------------------------------------------------------------
// Warp bitonic sort of 32*R u32 keys, ascending. Element i = lane*R + r.
// In-register passes exist ONLY for J < R (compile-time guarded — J >= R is
// handled by the cross-lane shfl passes; instantiating it would read OOB).
// ---------------------------------------------------------------------------
template<int R, int J>
__device__ __forceinline__ void inreg_pass(unsigned* key, int lane, int k) {
    if constexpr (J < R) {
        if (2 * J > k) return;
        #pragma unroll
        for (int r = 0; r < R; r++) {
            if ((r & J) == 0) {
                bool asc = (((unsigned)(lane * R + r) & (unsigned)k) == 0);
                unsigned a = key[r], b = key[r + J];
                unsigned mn = a < b ? a : b;
                unsigned mx = a < b ? b : a;
                key[r]     = asc ? mn : mx;
                key[r + J] = asc ? mx : mn;
            }
        }
    }
}

template<int R>
__device__ __forceinline__ void bitonic_sort_warp(unsigned* key) {
    const int lane = threadIdx.x & 31;
    const int N = 32 * R;
    for (int k = 2; k <= N; k <<= 1) {
        for (int m = (k >> 1) / R; m >= 1; m >>= 1) {
            #pragma unroll
            for (int r = 0; r < R; r++) {
                unsigned a = key[r];
                unsigned b = __shfl_xor_sync(0xffffffffu, a, m);
                bool asc   = (((unsigned)(lane * R + r) & (unsigned)k) == 0);
                bool lower = ((lane & m) == 0);
                unsigned mn = a < b ? a : b;
                unsigned mx = a < b ? b : a;
                key[r] = (lower == asc) ? mn : mx;
            }
        }
        inreg_pass<R, 8>(key, lane, k);
        inreg_pass<R, 4>(key, lane, k);
        inreg_pass<R, 2>(key, lane, k);
        inreg_pass<R, 1>(key, lane, k);
    }
}

// Ascending bitonic MERGE of 32*R elements held by one warp (j = 16R..1).
template<int R, int J>
__device__ __forceinline__ void inreg_merge_asc(unsigned* key) {
    if constexpr (J < R) {
        #pragma unroll
        for (int r = 0; r < R; r++) {
            if ((r & J) == 0) {
                unsigned a = key[r], b = key[r + J];
                key[r]     = a < b ? a : b;
                key[r + J] = a < b ? b : a;
            }
        }
    }
}

template<int R>
__device__ __forceinline__ void bitonic_merge_asc(unsigned* key) {
    const int lane = threadIdx.x & 31;
    #pragma unroll
    for (int m = 16; m >= 1; m >>= 1) {
        #pragma unroll
        for (int r = 0; r < R; r++) {
            unsigned a = key[r];
            unsigned b = __shfl_xor_sync(0xffffffffu, a, m);
            bool lower = ((lane & m) == 0);
            unsigned mn = a < b ? a : b;
            unsigned mx = a < b ? b : a;
            key[r] = lower ? mn : mx;
        }
    }
    inreg_merge_asc<R, 8>(key);
    inreg_merge_asc<R, 4>(key);
    inreg_merge_asc<R, 2>(key);
    inreg_merge_asc<R, 1>(key);
}

template<int R>
__device__ __forceinline__ void invert_keys(unsigned* key) {
    #pragma unroll
    for (int r = 0; r < R; r++) key[r] = ~key[r];
}

// ---------------------------------------------------------------------------
// Mega-fused kernel: 128-thread blocks (4 warps), ONE row per block, 1024
// blocks -> ~28 warps/SM. ALL warps cooperate in every sort (4-warp bitonic
// merge tree via double-buffered smem exchanges) and every walk. Masks are
// probed via LDG (32 KB, L1-resident after warm-up).
// ---------------------------------------------------------------------------
__global__ void __launch_bounds__(128) mega_kernel(const float* __restrict__ x,
                                                   float* __restrict__ out) {
    __shared__ unsigned      bufA[NIN];     // 2 KB — sort exchange / keys
    __shared__ unsigned      bufB[NIN];     // 2 KB — sort exchange / keys
    __shared__ float         vals[NIN];     // 2 KB
    __shared__ float         hrow[NHID];    // 1 KB
    __shared__ unsigned char sel1[NHID];
    __shared__ unsigned char sel2[NIN];

    const int tid  = threadIdx.x;      // 0..127
    const int w    = tid >> 5;         // warp 0..3
    const int lane = tid & 31;
    const int row  = blockIdx.x;

    // ============ Layer-1 sort: local R=4 sorts (alternating dir) ============
    unsigned key[4];
    {
        const float* src = x + (size_t)row * NIN + w * 128 + lane * 4;
        float4 v = *(const float4*)src;
        *(float4*)(&vals[w * 128 + lane * 4]) = v;
        float vv[4] = {v.x, v.y, v.z, v.w};
        #pragma unroll
        for (int q = 0; q < 4; q++) {
            int c = w * 128 + lane * 4 + q;
            key[q] = (__float_as_uint(vv[q]) & ~(unsigned)(NIN - 1)) | (unsigned)c;
        }
        // sel staging (precomputed by prep)
        if (tid < 64) ((unsigned*)sel1)[tid] = ((const unsigned*)g_sel1)[tid];
        ((unsigned*)sel2)[tid] = ((const unsigned*)g_sel2)[tid];

        if (w & 1) invert_keys<4>(key);
        bitonic_sort_warp<4>(key);
        if (w & 1) invert_keys<4>(key);    // odd warps descending
        #pragma unroll
        for (int r = 0; r < 4; r++) bufA[w * 128 + lane * 4 + r] = key[r];
    }
    __syncthreads();

    // ---- stage k=256: j=128 (partner w^1), then warp-local merge ------------
    {
        const bool desc = (w >= 2);            // (p & 256) != 0
        const int  pw   = w ^ 1;
        const bool keepmin = ((w < pw) != desc);
        #pragma unroll
        for (int r = 0; r < 4; r++) {
            unsigned p = bufA[pw * 128 + lane * 4 + r];
            unsigned a = key[r];
            key[r] = keepmin ? (a < p ? a : p) : (a > p ? a : p);
        }
        if (desc) invert_keys<4>(key);
        bitonic_merge_asc<4>(key);
        if (desc) invert_keys<4>(key);
        #pragma unroll
        for (int r = 0; r < 4; r++) bufB[w * 128 + lane * 4 + r] = key[r];
    }
    __syncthreads();

    // ---- stage k=512: j=256 (partner w^2), all ascending ---------------------
    {
        const int pw = w ^ 2;
        const bool keepmin = (w < pw);
        #pragma unroll
        for (int r = 0; r < 4; r++) {
            unsigned p = bufB[pw * 128 + lane * 4 + r];
            unsigned a = key[r];
            key[r] = keepmin ? (a < p ? a : p) : (a > p ? a : p);
        }
        #pragma unroll
        for (int r = 0; r < 4; r++) bufA[w * 128 + lane * 4 + r] = key[r];
    }
    __syncthreads();

    // ---- j=128 (partner w^1) + warp-local merge; final keys -> bufB ----------
    {
        const int pw = w ^ 1;
        const bool keepmin = (w < pw);
        #pragma unroll
        for (int r = 0; r < 4; r++) {
            unsigned p = bufA[pw * 128 + lane * 4 + r];
            unsigned a = key[r];
            key[r] = keepmin ? (a < p ? a : p) : (a > p ? a : p);
        }
        bitonic_merge_asc<4>(key);
        #pragma unroll
        for (int r = 0; r < 4; r++) bufB[w * 128 + lane * 4 + r] = key[r];
    }
    __syncthreads();

    // ============ Layer-1 walk: 2 node-chains per thread ======================
    {
        bool s[2]; float v[2]; bool f[2];
        #pragma unroll
        for (int c = 0; c < 2; c++) {
            int node = c * 128 + tid;
            s[c] = sel1[node] != 0;
            v[c] = s[c] ? 0.0f : 1.0f;     // empty-mask identity
            f[c] = false;
        }
        for (int t = 0; t < NIN; t++) {
            int iA = (int)(bufB[t] & (unsigned)(NIN - 1));             // min probe
            int iB = (int)(bufB[(NIN - 1) - t] & (unsigned)(NIN - 1)); // max probe
            bool alldone = true;
            #pragma unroll
            for (int c = 0; c < 2; c++) {
                if (!f[c]) {
                    int node = c * 128 + tid;
                    int idx  = s[c] ? iB : iA;
                    unsigned m = g_mT1[(idx >> 5) * NHID + node];   // L1-resident
                    if ((m >> (idx & 31)) & 1u) { v[c] = vals[idx]; f[c] = true; }
                }
                alldone &= f[c];
            }
            if (alldone) break;
        }
        #pragma unroll
        for (int c = 0; c < 2; c++)
            hrow[c * 128 + tid] = fmaxf(v[c], 0.0f);
    }
    __syncthreads();

    // ============ Layer-2 sort: 4-warp, 64 elements/warp (R=2) ================
    unsigned k2[2];
    {
        #pragma unroll
        for (int r = 0; r < 2; r++) {
            int c = w * 64 + lane * 2 + r;
            k2[r] = (__float_as_uint(hrow[c]) & ~(unsigned)(NHID - 1)) | (unsigned)c;
        }
        if (w & 1) invert_keys<2>(k2);
        bitonic_sort_warp<2>(k2);
        if (w & 1) invert_keys<2>(k2);
        #pragma unroll
        for (int r = 0; r < 2; r++) bufA[w * 64 + lane * 2 + r] = k2[r];
    }
    __syncthreads();
    {   // stage k=128: j=64 (partner w^1), local merge with region dir
        const bool desc = (w >= 2);            // (p & 128) != 0
        const int  pw   = w ^ 1;
        const bool keepmin = ((w < pw) != desc);
        #pragma unroll
        for (int r = 0; r < 2; r++) {
            unsigned p = bufA[pw * 64 + lane * 2 + r];
            unsigned a = k2[r];
            k2[r] = keepmin ? (a < p ? a : p) : (a > p ? a : p);
        }
        if (desc) invert_keys<2>(k2);
        bitonic_merge_asc<2>(k2);
        if (desc) invert_keys<2>(k2);
        #pragma unroll
        for (int r = 0; r < 2; r++) bufB[w * 64 + lane * 2 + r] = k2[r];
    }
    __syncthreads();
    {   // stage k=256: j=128 (partner w^2), ascending
        const int pw = w ^ 2;
        const bool keepmin = (w < pw);
        #pragma unroll
        for (int r = 0; r < 2; r++) {
            unsigned p = bufB[pw * 64 + lane * 2 + r];
            unsigned a = k2[r];
            k2[r] = keepmin ? (a < p ? a : p) : (a > p ? a : p);
        }
        #pragma unroll
        for (int r = 0; r < 2; r++) bufA[w * 64 + lane * 2 + r] = k2[r];
    }
    __syncthreads();
    {   // j=64 (partner w^1) + local merge asc; final keys -> bufB
        const int pw = w ^ 1;
        const bool keepmin = (w < pw);
        #pragma unroll
        for (int r = 0; r < 2; r++) {
            unsigned p = bufA[pw * 64 + lane * 2 + r];
            unsigned a = k2[r];
            k2[r] = keepmin ? (a < p ? a : p) : (a > p ? a : p);
        }
        bitonic_merge_asc<2>(k2);
        #pragma unroll
        for (int r = 0; r < 2; r++) bufB[w * 64 + lane * 2 + r] = k2[r];
    }
    __syncthreads();

    // ============ Layer-2 walk: 4 node-chains per thread ======================
    {
        bool s[4]; float v[4]; bool f[4];
        #pragma unroll
        for (int c = 0; c < 4; c++) {
            int node = c * 128 + tid;
            s[c] = sel2[node] != 0;
            v[c] = s[c] ? 0.0f : 1.0f;
            f[c] = false;
        }
        for (int t = 0; t < NHID; t++) {
            int iA = (int)(bufB[t] & (unsigned)(NHID - 1));
            int iB = (int)(bufB[(NHID - 1) - t] & (unsigned)(NHID - 1));
            bool alldone = true;
            #pragma unroll
            for (int c = 0; c < 4; c++) {
                if (!f[c]) {
                    int node = c * 128 + tid;
                    int idx  = s[c] ? iB : iA;
                    unsigned m = g_mT2[(idx >> 5) * NIN + node];    // L1-resident
                    if ((m >> (idx & 31)) & 1u) { v[c] = hrow[idx]; f[c] = true; }
                }
                alldone &= f[c];
            }
            if (alldone) break;
        }
        #pragma unroll
        for (int c = 0; c < 4; c++)
            out[(size_t)row * NIN + c * 128 + tid] = fmaxf(v[c], 0.0f);
    }
}

// ---------------------------------------------------------------------------
// kernel_launch: prep (masks + sel) -> mega (both layers). Two launches.
// ---------------------------------------------------------------------------
extern "C" void kernel_launch(void* const* d_in, const int* in_sizes, int n_in,
                              void* d_out, int out_size) {
    const float* x       = (const float*)d_in[0];
    const float* logits1 = (const float*)d_in[1];
    const float* u1      = (const float*)d_in[2];
    const float* logits2 = (const float*)d_in[3];
    const float* u2      = (const float*)d_in[4];
    const void*  mask1   = d_in[5];
    const void*  mask2   = d_in[6];
    float* out = (float*)d_out;
    (void)in_sizes; (void)n_in; (void)out_size;

    prep_kernel<<<257, 256>>>(mask1, mask2, logits1, u1, logits2, u2);
    mega_kernel<<<BATCH, 128>>>(x, out);
}